// round 13
// baseline (speedup 1.0000x reference)
#include <cuda_runtime.h>
#include <cuda_bf16.h>

// IDWT 2D (inverse Haar), reference-exact layout. R11 kernel (best: 43.5us,
// R3 shape + __stcs output demotion) with ONE change: 512-thread blocks
// (was 256). Work mapping is tid-based, so coalescing/correctness are
// bit-identical; larger blocks halve CTA-scheduling events and lengthen
// per-CTA same-direction DRAM bursts (16 warps of front-batched LDGs per
// CTA arrival instead of 8). regs=20 -> 2x512-thread CTAs hit the 32-warp
// cap, same theoretical occupancy as 8x256.
//
// Input x: (B=8, 4*C=256, H=128, W=128) fp32 -> Output (8, 64, 256, 256) fp32.
// Mapping from the reference's raw (H,W,2,2)->(2H,2W) reshape:
//   j in [0,64):   row = 2i,   col = 4j       (+2a+b)
//   j in [64,128): row = 2i+1, col = 4(j-64)  (+2a+b)
// Butterfly order: (ll+lh+hl+hh, ll+lh-hl-hh, ll-lh+hl-hh, ll-lh-hl+hh).

static constexpr int B  = 8;
static constexpr int C  = 64;
static constexpr int H  = 128;
static constexpr int W  = 128;
static constexpr int JV = W / 2;   // 64 j-pairs per input row

static constexpr long long BAND_STRIDE = (long long)C * H * W;   // 1,048,576
static constexpr long long X_N_STRIDE  = 4LL * BAND_STRIDE;
static constexpr long long O_C_STRIDE  = 2LL * H * 2LL * W;      // 65,536
static constexpr long long O_N_STRIDE  = (long long)C * O_C_STRIDE;

__global__ void __launch_bounds__(512) idwt2d_kernel(const float* __restrict__ x,
                                                     float* __restrict__ out)
{
    // total threads = B*C*H*JV = 4,194,304; one thread per j-pair
    int tid = blockIdx.x * blockDim.x + threadIdx.x;

    int jv = tid & (JV - 1);         // 0..63  -> j = 2jv, 2jv+1
    int t1 = tid >> 6;
    int i  = t1 & (H - 1);           // 0..127
    int t2 = t1 >> 7;
    int c  = t2 & (C - 1);           // 0..63
    int n  = t2 >> 6;                // 0..7

    long long xbase = (long long)n * X_N_STRIDE
                    + (long long)c * H * W
                    + (long long)i * W
                    + 2 * jv;

    float2 ll = __ldg((const float2*)(x + xbase + 0 * BAND_STRIDE));
    float2 lh = __ldg((const float2*)(x + xbase + 1 * BAND_STRIDE));
    float2 hl = __ldg((const float2*)(x + xbase + 2 * BAND_STRIDE));
    float2 hh = __ldg((const float2*)(x + xbase + 3 * BAND_STRIDE));

    // butterfly for j = 2jv (x) and j = 2jv+1 (y)
    float sA0 = ll.x + lh.x, dA0 = ll.x - lh.x;
    float sB0 = hl.x + hh.x, dB0 = hl.x - hh.x;
    float sA1 = ll.y + lh.y, dA1 = ll.y - lh.y;
    float sB1 = hl.y + hh.y, dB1 = hl.y - hh.y;

    float4 q0, q1;
    q0.x = sA0 + sB0;   // (a,b)=(0,0)
    q0.y = sA0 - sB0;   // (0,1)
    q0.z = dA0 + dB0;   // (1,0)
    q0.w = dA0 - dB0;   // (1,1)

    q1.x = sA1 + sB1;
    q1.y = sA1 - sB1;
    q1.z = dA1 + dB1;
    q1.w = dA1 - dB1;

    // j = 2jv -> row = 2i + (jv>=32), col = 4*((2jv) mod 64)
    int jhalf = jv >> 5;
    int col   = (2 * jv - jhalf * 64) * 4;

    long long obase = (long long)n * O_N_STRIDE
                    + (long long)c * O_C_STRIDE
                    + (long long)(2 * i + jhalf) * (2 * W)
                    + col;

    __stcs((float4*)(out + obase),     q0);
    __stcs((float4*)(out + obase + 4), q1);
}

extern "C" void kernel_launch(void* const* d_in, const int* in_sizes, int n_in,
                              void* d_out, int out_size)
{
    const float* x = (const float*)d_in[0];
    float* out = (float*)d_out;

    const int total = B * C * H * JV;   // 4,194,304
    const int threads = 512;
    const int blocks = total / threads; // 8192

    idwt2d_kernel<<<blocks, threads>>>(x, out);
}